// round 1
// baseline (speedup 1.0000x reference)
#include <cuda_runtime.h>
#include <cuda_bf16.h>

#define NF 64
#define NG 64
#define NW 64
#define NBATCH 32768
#define ROWS 128
#define NTHREADS 256
#define NCTA (NBATCH / ROWS)
#define CPAD 72   // padded coef row stride in ushort elements (144 bytes)

// Scratch (allocation-free rule: device globals)
__device__ unsigned short g_coef[NF * NG * NW];  // bf16 bits, [f][g][w]
__device__ float g_Wt[NF * NW];                  // transposed skip weights [f][w]

// ---------------------------------------------------------------------------
// Prep: convert spline coeffs to bf16, transpose skip_W. Runs every launch
// (deterministic, graph-capturable).
// ---------------------------------------------------------------------------
__global__ void prep_kernel(const float* __restrict__ coef,
                            const float* __restrict__ skipW) {
    int i0 = blockIdx.x * blockDim.x + threadIdx.x;
    int stride = gridDim.x * blockDim.x;
    for (int i = i0; i < NF * NG * NW; i += stride) {
        __nv_bfloat16 h = __float2bfloat16(coef[i]);
        g_coef[i] = *reinterpret_cast<unsigned short*>(&h);
    }
    if (i0 < NF * NW) {
        int f = i0 >> 6, w = i0 & 63;
        g_Wt[i0] = skipW[w * NF + f];
    }
}

__device__ __forceinline__ unsigned smem_u32(const void* p) {
    return (unsigned)__cvta_generic_to_shared(p);
}

// Stage one feature's 64x64 bf16 coef tile (8 KB) into padded SMEM rows.
// 512 16-byte chunks over 256 threads = 2 chunks/thread.
__device__ __forceinline__ void prefetch_coef(unsigned short (*Cs)[NG * CPAD],
                                              int buf, int f, int tid) {
    const unsigned short* src = g_coef + f * (NG * NW);
#pragma unroll
    for (int q = 0; q < 2; q++) {
        int ch = tid * 2 + q;     // 0..511
        int gr = ch >> 3;         // grid row 0..63
        int cw = ch & 7;          // 16B chunk within row
        unsigned dst = smem_u32(&Cs[buf][gr * CPAD + cw * 8]);
        const void* s = src + gr * NW + cw * 8;
        asm volatile("cp.async.cg.shared.global [%0], [%1], 16;" ::"r"(dst), "l"(s));
    }
    asm volatile("cp.async.commit_group;");
}

// ---------------------------------------------------------------------------
// Fused KAN layer: sigmoid-normalise -> sparse cubic B-spline mix (bf16 coefs,
// fp32 accum) + skip GEMM + bias -> LayerNorm -> exact GELU.
// 1 CTA = 128 rows; 1 thread = 1 row-half (32 output cols, 32 fp32 accs).
// ---------------------------------------------------------------------------
__global__ void __launch_bounds__(NTHREADS) kan_kernel(
    const float* __restrict__ X,
    const float* __restrict__ shift,
    const float* __restrict__ lscale,
    const float* __restrict__ skip_b,
    const float* __restrict__ bias,
    const float* __restrict__ gamma,
    const float* __restrict__ beta,
    const float* __restrict__ knots,
    float* __restrict__ out) {
    __shared__ __align__(16) unsigned short Cs[2][NG * CPAD];  // double-buffered coef tile
    __shared__ float kn[68];
    __shared__ float rcp6[61 * 6];   // per-interval de Boor reciprocal denominators
    __shared__ float sh_s[64], sc_s[64], cb_s[64], ga_s[64], be_s[64];

    const int tid = threadIdx.x;
    const int row = tid >> 1;
    const int half = tid & 1;
    const int wc = half * 32;
    const int rg = blockIdx.x * ROWS + row;

    if (tid < 68) kn[tid] = knots[tid];
    if (tid < 64) {
        sh_s[tid] = shift[tid];
        sc_s[tid] = log1pf(__expf(lscale[tid])) + 0.001f;  // softplus + 1e-3
        cb_s[tid] = skip_b[tid] + bias[tid];
        ga_s[tid] = gamma[tid];
        be_s[tid] = beta[tid];
    }
    __syncthreads();
    if (tid < 61) {
        int j = tid + 3;
        rcp6[tid * 6 + 0] = 1.0f / (kn[j + 1] - kn[j]);
        rcp6[tid * 6 + 1] = 1.0f / (kn[j + 1] - kn[j - 1]);
        rcp6[tid * 6 + 2] = 1.0f / (kn[j + 2] - kn[j]);
        rcp6[tid * 6 + 3] = 1.0f / (kn[j + 1] - kn[j - 2]);
        rcp6[tid * 6 + 4] = 1.0f / (kn[j + 2] - kn[j - 1]);
        rcp6[tid * 6 + 5] = 1.0f / (kn[j + 3] - kn[j]);
    }

    float acc[32];
#pragma unroll
    for (int c = 0; c < 32; c++) acc[c] = cb_s[wc + c];  // skip_b + bias

    prefetch_coef(Cs, 0, 0, tid);
    __syncthreads();  // covers rcp6 + first compute ordering

    const float* xrow = X + rg * NF;

    for (int f = 0; f < NF; f++) {
        if (f + 1 < NF) {
            prefetch_coef(Cs, (f + 1) & 1, f + 1, tid);
            asm volatile("cp.async.wait_group 1;");
        } else {
            asm volatile("cp.async.wait_group 0;");
        }
        __syncthreads();

        float xr = __ldg(xrow + f);
        float arg = (xr - sh_s[f]) * sc_s[f];
        float e = __expf(-arg);
        float xs = __fdividef(1.0f, 1.0f + e);  // sigmoid, in (0,1)

        // interval: knots uniform on [0,1] with 61 spans; clamp for safety
        int jj = (int)(xs * 61.0f);
        jj = jj < 60 ? jj : 60;
        jj = jj < 0 ? 0 : jj;
        const int j = jj + 3;
        const float* rc = &rcp6[jj * 6];

        // Cox–de Boor: 4 nonzero cubic basis values N0..N3 for g = jj..jj+3
        float l1 = xs - kn[j], l2 = xs - kn[j - 1], l3 = xs - kn[j - 2];
        float r1 = kn[j + 1] - xs, r2 = kn[j + 2] - xs, r3 = kn[j + 3] - xs;
        float t = rc[0];
        float N0 = r1 * t, N1 = l1 * t;
        t = N0 * rc[1]; N0 = r1 * t; float sv = l2 * t;
        t = N1 * rc[2]; N1 = sv + r2 * t; float N2 = l1 * t;
        t = N0 * rc[3]; N0 = r1 * t; sv = l3 * t;
        t = N1 * rc[4]; N1 = sv + r2 * t; sv = l2 * t;
        t = N2 * rc[5]; N2 = sv + r3 * t; float N3 = l1 * t;

        const unsigned short* Cb = Cs[f & 1];
        float bw4[4] = {N0, N1, N2, N3};
#pragma unroll
        for (int k = 0; k < 4; k++) {
            const uint4* cp4 =
                reinterpret_cast<const uint4*>(Cb + (jj + k) * CPAD + wc);
            float bk = bw4[k];
#pragma unroll
            for (int q = 0; q < 4; q++) {
                uint4 v = cp4[q];
                int c = q * 8;
                acc[c + 0] += bk * __uint_as_float(v.x << 16);
                acc[c + 1] += bk * __uint_as_float(v.x & 0xffff0000u);
                acc[c + 2] += bk * __uint_as_float(v.y << 16);
                acc[c + 3] += bk * __uint_as_float(v.y & 0xffff0000u);
                acc[c + 4] += bk * __uint_as_float(v.z << 16);
                acc[c + 5] += bk * __uint_as_float(v.z & 0xffff0000u);
                acc[c + 6] += bk * __uint_as_float(v.w << 16);
                acc[c + 7] += bk * __uint_as_float(v.w & 0xffff0000u);
            }
        }

        // skip connection: rank-1 update x[f] * Wt[f, :] (fp32, L1-resident)
        const float4* wp = reinterpret_cast<const float4*>(g_Wt + f * NW + wc);
#pragma unroll
        for (int q = 0; q < 8; q++) {
            float4 wv = __ldg(wp + q);
            int c = q * 4;
            acc[c + 0] += xr * wv.x;
            acc[c + 1] += xr * wv.y;
            acc[c + 2] += xr * wv.z;
            acc[c + 3] += xr * wv.w;
        }
        __syncthreads();  // buffer f&1 fully consumed before it is refilled
    }

    // LayerNorm over 64 cols: pair-reduce with partner lane (other half of row)
    float s = 0.f, sq = 0.f;
#pragma unroll
    for (int c = 0; c < 32; c++) {
        s += acc[c];
        sq += acc[c] * acc[c];
    }
    s += __shfl_xor_sync(0xffffffffu, s, 1);
    sq += __shfl_xor_sync(0xffffffffu, sq, 1);
    float mean = s * (1.0f / 64.0f);
    float var = sq * (1.0f / 64.0f) - mean * mean;
    var = fmaxf(var, 0.0f);
    float inv = rsqrtf(var + 1e-5f);

    float4* og = reinterpret_cast<float4*>(out + rg * NW + wc);
#pragma unroll
    for (int q = 0; q < 8; q++) {
        int c = q * 4;
        float4 o;
        float y0 = (acc[c + 0] - mean) * inv * ga_s[wc + c + 0] + be_s[wc + c + 0];
        float y1 = (acc[c + 1] - mean) * inv * ga_s[wc + c + 1] + be_s[wc + c + 1];
        float y2 = (acc[c + 2] - mean) * inv * ga_s[wc + c + 2] + be_s[wc + c + 2];
        float y3 = (acc[c + 3] - mean) * inv * ga_s[wc + c + 3] + be_s[wc + c + 3];
        o.x = 0.5f * y0 * (1.0f + erff(y0 * 0.70710678118654752f));
        o.y = 0.5f * y1 * (1.0f + erff(y1 * 0.70710678118654752f));
        o.z = 0.5f * y2 * (1.0f + erff(y2 * 0.70710678118654752f));
        o.w = 0.5f * y3 * (1.0f + erff(y3 * 0.70710678118654752f));
        og[q] = o;
    }
}

extern "C" void kernel_launch(void* const* d_in, const int* in_sizes, int n_in,
                              void* d_out, int out_size) {
    const float* X      = (const float*)d_in[0];
    const float* shift  = (const float*)d_in[1];
    const float* lscale = (const float*)d_in[2];
    const float* coef   = (const float*)d_in[3];
    const float* skipW  = (const float*)d_in[4];
    const float* skipb  = (const float*)d_in[5];
    const float* bias   = (const float*)d_in[6];
    const float* gam    = (const float*)d_in[7];
    const float* bet    = (const float*)d_in[8];
    const float* knots  = (const float*)d_in[9];

    prep_kernel<<<256, 256>>>(coef, skipW);
    kan_kernel<<<NCTA, NTHREADS>>>(X, shift, lscale, skipb, bias, gam, bet,
                                   knots, (float*)d_out);
}

// round 2
// speedup vs baseline: 1.0004x; 1.0004x over previous
#include <cuda_runtime.h>
#include <cuda_bf16.h>

#define NF 64
#define NG 64
#define NW 64
#define NBATCH 32768
#define ROWS 128
#define NTHREADS 256
#define NCTA (NBATCH / ROWS)
#define CPAD 72   // padded coef row stride in ushort elements (144 bytes)

// Scratch (allocation-free rule: device globals)
__device__ unsigned short g_coef[NF * NG * NW];  // bf16 bits, [f][g][w]
__device__ float g_Wt[NF * NW];                  // transposed skip weights [f][w]

// ---------------------------------------------------------------------------
// Prep: convert spline coeffs to bf16, transpose skip_W. Runs every launch
// (deterministic, graph-capturable).
// ---------------------------------------------------------------------------
__global__ void prep_kernel(const float* __restrict__ coef,
                            const float* __restrict__ skipW) {
    int i0 = blockIdx.x * blockDim.x + threadIdx.x;
    int stride = gridDim.x * blockDim.x;
    for (int i = i0; i < NF * NG * NW; i += stride) {
        __nv_bfloat16 h = __float2bfloat16(coef[i]);
        g_coef[i] = *reinterpret_cast<unsigned short*>(&h);
    }
    if (i0 < NF * NW) {
        int f = i0 >> 6, w = i0 & 63;
        g_Wt[i0] = skipW[w * NF + f];
    }
}

__device__ __forceinline__ unsigned smem_u32(const void* p) {
    return (unsigned)__cvta_generic_to_shared(p);
}

// Stage one feature's 64x64 bf16 coef tile (8 KB) into padded SMEM rows.
// 512 16-byte chunks over 256 threads = 2 chunks/thread.
__device__ __forceinline__ void prefetch_coef(unsigned short (*Cs)[NG * CPAD],
                                              int buf, int f, int tid) {
    const unsigned short* src = g_coef + f * (NG * NW);
#pragma unroll
    for (int q = 0; q < 2; q++) {
        int ch = tid * 2 + q;     // 0..511
        int gr = ch >> 3;         // grid row 0..63
        int cw = ch & 7;          // 16B chunk within row
        unsigned dst = smem_u32(&Cs[buf][gr * CPAD + cw * 8]);
        const void* s = src + gr * NW + cw * 8;
        asm volatile("cp.async.cg.shared.global [%0], [%1], 16;" ::"r"(dst), "l"(s));
    }
    asm volatile("cp.async.commit_group;");
}

// ---------------------------------------------------------------------------
// Fused KAN layer: sigmoid-normalise -> sparse cubic B-spline mix (bf16 coefs,
// fp32 accum) + skip GEMM + bias -> LayerNorm -> exact GELU.
// 1 CTA = 128 rows; 1 thread = 1 row-half (32 output cols, 32 fp32 accs).
// ---------------------------------------------------------------------------
__global__ void __launch_bounds__(NTHREADS) kan_kernel(
    const float* __restrict__ X,
    const float* __restrict__ shift,
    const float* __restrict__ lscale,
    const float* __restrict__ skip_b,
    const float* __restrict__ bias,
    const float* __restrict__ gamma,
    const float* __restrict__ beta,
    const float* __restrict__ knots,
    float* __restrict__ out) {
    __shared__ __align__(16) unsigned short Cs[2][NG * CPAD];  // double-buffered coef tile
    __shared__ float kn[68];
    __shared__ float rcp6[61 * 6];   // per-interval de Boor reciprocal denominators
    __shared__ float sh_s[64], sc_s[64], cb_s[64], ga_s[64], be_s[64];

    const int tid = threadIdx.x;
    const int row = tid >> 1;
    const int half = tid & 1;
    const int wc = half * 32;
    const int rg = blockIdx.x * ROWS + row;

    if (tid < 68) kn[tid] = knots[tid];
    if (tid < 64) {
        sh_s[tid] = shift[tid];
        sc_s[tid] = log1pf(__expf(lscale[tid])) + 0.001f;  // softplus + 1e-3
        cb_s[tid] = skip_b[tid] + bias[tid];
        ga_s[tid] = gamma[tid];
        be_s[tid] = beta[tid];
    }
    __syncthreads();
    if (tid < 61) {
        int j = tid + 3;
        rcp6[tid * 6 + 0] = 1.0f / (kn[j + 1] - kn[j]);
        rcp6[tid * 6 + 1] = 1.0f / (kn[j + 1] - kn[j - 1]);
        rcp6[tid * 6 + 2] = 1.0f / (kn[j + 2] - kn[j]);
        rcp6[tid * 6 + 3] = 1.0f / (kn[j + 1] - kn[j - 2]);
        rcp6[tid * 6 + 4] = 1.0f / (kn[j + 2] - kn[j - 1]);
        rcp6[tid * 6 + 5] = 1.0f / (kn[j + 3] - kn[j]);
    }

    float acc[32];
#pragma unroll
    for (int c = 0; c < 32; c++) acc[c] = cb_s[wc + c];  // skip_b + bias

    prefetch_coef(Cs, 0, 0, tid);
    __syncthreads();  // covers rcp6 + first compute ordering

    const float* xrow = X + rg * NF;

    for (int f = 0; f < NF; f++) {
        if (f + 1 < NF) {
            prefetch_coef(Cs, (f + 1) & 1, f + 1, tid);
            asm volatile("cp.async.wait_group 1;");
        } else {
            asm volatile("cp.async.wait_group 0;");
        }
        __syncthreads();

        float xr = __ldg(xrow + f);
        float arg = (xr - sh_s[f]) * sc_s[f];
        float e = __expf(-arg);
        float xs = __fdividef(1.0f, 1.0f + e);  // sigmoid, in (0,1)

        // interval: knots uniform on [0,1] with 61 spans; clamp for safety
        int jj = (int)(xs * 61.0f);
        jj = jj < 60 ? jj : 60;
        jj = jj < 0 ? 0 : jj;
        const int j = jj + 3;
        const float* rc = &rcp6[jj * 6];

        // Cox–de Boor: 4 nonzero cubic basis values N0..N3 for g = jj..jj+3
        float l1 = xs - kn[j], l2 = xs - kn[j - 1], l3 = xs - kn[j - 2];
        float r1 = kn[j + 1] - xs, r2 = kn[j + 2] - xs, r3 = kn[j + 3] - xs;
        float t = rc[0];
        float N0 = r1 * t, N1 = l1 * t;
        t = N0 * rc[1]; N0 = r1 * t; float sv = l2 * t;
        t = N1 * rc[2]; N1 = sv + r2 * t; float N2 = l1 * t;
        t = N0 * rc[3]; N0 = r1 * t; sv = l3 * t;
        t = N1 * rc[4]; N1 = sv + r2 * t; sv = l2 * t;
        t = N2 * rc[5]; N2 = sv + r3 * t; float N3 = l1 * t;

        const unsigned short* Cb = Cs[f & 1];
        float bw4[4] = {N0, N1, N2, N3};
#pragma unroll
        for (int k = 0; k < 4; k++) {
            const uint4* cp4 =
                reinterpret_cast<const uint4*>(Cb + (jj + k) * CPAD + wc);
            float bk = bw4[k];
#pragma unroll
            for (int q = 0; q < 4; q++) {
                uint4 v = cp4[q];
                int c = q * 8;
                acc[c + 0] += bk * __uint_as_float(v.x << 16);
                acc[c + 1] += bk * __uint_as_float(v.x & 0xffff0000u);
                acc[c + 2] += bk * __uint_as_float(v.y << 16);
                acc[c + 3] += bk * __uint_as_float(v.y & 0xffff0000u);
                acc[c + 4] += bk * __uint_as_float(v.z << 16);
                acc[c + 5] += bk * __uint_as_float(v.z & 0xffff0000u);
                acc[c + 6] += bk * __uint_as_float(v.w << 16);
                acc[c + 7] += bk * __uint_as_float(v.w & 0xffff0000u);
            }
        }

        // skip connection: rank-1 update x[f] * Wt[f, :] (fp32, L1-resident)
        const float4* wp = reinterpret_cast<const float4*>(g_Wt + f * NW + wc);
#pragma unroll
        for (int q = 0; q < 8; q++) {
            float4 wv = __ldg(wp + q);
            int c = q * 4;
            acc[c + 0] += xr * wv.x;
            acc[c + 1] += xr * wv.y;
            acc[c + 2] += xr * wv.z;
            acc[c + 3] += xr * wv.w;
        }
        __syncthreads();  // buffer f&1 fully consumed before it is refilled
    }

    // LayerNorm over 64 cols: pair-reduce with partner lane (other half of row)
    float s = 0.f, sq = 0.f;
#pragma unroll
    for (int c = 0; c < 32; c++) {
        s += acc[c];
        sq += acc[c] * acc[c];
    }
    s += __shfl_xor_sync(0xffffffffu, s, 1);
    sq += __shfl_xor_sync(0xffffffffu, sq, 1);
    float mean = s * (1.0f / 64.0f);
    float var = sq * (1.0f / 64.0f) - mean * mean;
    var = fmaxf(var, 0.0f);
    float inv = rsqrtf(var + 1e-5f);

    float4* og = reinterpret_cast<float4*>(out + rg * NW + wc);
#pragma unroll
    for (int q = 0; q < 8; q++) {
        int c = q * 4;
        float4 o;
        float y0 = (acc[c + 0] - mean) * inv * ga_s[wc + c + 0] + be_s[wc + c + 0];
        float y1 = (acc[c + 1] - mean) * inv * ga_s[wc + c + 1] + be_s[wc + c + 1];
        float y2 = (acc[c + 2] - mean) * inv * ga_s[wc + c + 2] + be_s[wc + c + 2];
        float y3 = (acc[c + 3] - mean) * inv * ga_s[wc + c + 3] + be_s[wc + c + 3];
        o.x = 0.5f * y0 * (1.0f + erff(y0 * 0.70710678118654752f));
        o.y = 0.5f * y1 * (1.0f + erff(y1 * 0.70710678118654752f));
        o.z = 0.5f * y2 * (1.0f + erff(y2 * 0.70710678118654752f));
        o.w = 0.5f * y3 * (1.0f + erff(y3 * 0.70710678118654752f));
        og[q] = o;
    }
}

extern "C" void kernel_launch(void* const* d_in, const int* in_sizes, int n_in,
                              void* d_out, int out_size) {
    const float* X      = (const float*)d_in[0];
    const float* shift  = (const float*)d_in[1];
    const float* lscale = (const float*)d_in[2];
    const float* coef   = (const float*)d_in[3];
    const float* skipW  = (const float*)d_in[4];
    const float* skipb  = (const float*)d_in[5];
    const float* bias   = (const float*)d_in[6];
    const float* gam    = (const float*)d_in[7];
    const float* bet    = (const float*)d_in[8];
    const float* knots  = (const float*)d_in[9];

    prep_kernel<<<256, 256>>>(coef, skipW);
    kan_kernel<<<NCTA, NTHREADS>>>(X, shift, lscale, skipb, bias, gam, bet,
                                   knots, (float*)d_out);
}

// round 4
// speedup vs baseline: 1.3804x; 1.3797x over previous
#include <cuda_runtime.h>
#include <cuda_bf16.h>
#include <cstdint>

#define NF 64
#define NW 64
#define NBATCH 32768
#define ROWS 128
#define NCTA (NBATCH / ROWS)
#define NTHREADS 256

// ---------------- dynamic SMEM layout (offsets from 1024-aligned base) ------
// A region doubles as X hi/lo staging (prologue) then basis double buffer.
#define OF_A0   0
#define OF_A1   16384
#define OF_WHI  32768
#define OF_WLO  40960
#define OF_C(s) (49152 + (s) * 8192)    // coef ring, 4 slots, through 81920
#define OF_D    32768                    // f32 D[128][65] overlay (epilogue only)
#define DSTRIDE 65
#define DYN_BYTES (81920 + 1024)

// ---------------- device globals (allocation-free scratch) ------------------
__device__ __align__(16) unsigned short g_coefB[NF * 64 * 64];  // bf16, pre-swizzled [f][w][g]

__device__ __forceinline__ unsigned su(const void* p) {
    return (unsigned)__cvta_generic_to_shared(p);
}
__device__ __forceinline__ unsigned short bfbits(float x) {
    __nv_bfloat16 h = __float2bfloat16(x);
    return *reinterpret_cast<unsigned short*>(&h);
}
__device__ __forceinline__ float bfround(float x) {
    return __bfloat162float(__float2bfloat16(x));
}

// ---------------------------------------------------------------------------
// Prep: spline_coeffs [f][g][w] fp32 -> bf16 B-tiles [f][w-row][g-col],
// SW128 pre-swizzled so a linear cp.async lands them ldmatrix-ready.
// ---------------------------------------------------------------------------
__global__ void prep_kernel(const float* __restrict__ coef) {
    int i0 = blockIdx.x * blockDim.x + threadIdx.x;
    int stride = gridDim.x * blockDim.x;
    for (int i = i0; i < NF * 64 * 64; i += stride) {
        int f = i >> 12, rem = i & 4095, g = rem >> 6, w = rem & 63;
        unsigned o = (unsigned)w * 128u + ((2u * (unsigned)g) ^ (((unsigned)w & 7u) << 4));
        g_coefB[(f << 12) + (o >> 1)] = bfbits(coef[i]);
    }
}

// 8KB coef tile f -> SMEM slot via cp.async (2 x 16B per thread)
__device__ __forceinline__ void cpa_coef(char* dynp, int slot, int f, int tid) {
    unsigned dst = su(dynp + OF_C(slot)) + tid * 16;
    const char* src = (const char*)(g_coefB + ((size_t)f << 12)) + tid * 16;
    asm volatile(
        "cp.async.cg.shared.global [%0], [%1], 16;\n\t"
        "cp.async.cg.shared.global [%2], [%3], 16;"
        :: "r"(dst), "l"(src), "r"(dst + 4096), "l"(src + 4096) : "memory");
}

__device__ __forceinline__ void hmma(float (&c)[4], const unsigned (&a)[4],
                                     const unsigned (&b)[2]) {
    asm volatile(
        "mma.sync.aligned.m16n8k16.row.col.f32.bf16.bf16.f32 "
        "{%0,%1,%2,%3}, {%4,%5,%6,%7}, {%8,%9}, {%0,%1,%2,%3};"
        : "+f"(c[0]), "+f"(c[1]), "+f"(c[2]), "+f"(c[3])
        : "r"(a[0]), "r"(a[1]), "r"(a[2]), "r"(a[3]), "r"(b[0]), "r"(b[1]));
}

// One 128x64 @ 64x64 -> 128x64 GEMM step for this warp (warp tile 32x32).
// A tile: [row][k] bf16, 128B rows, SW128.  B tile: [n][k] bf16, 128B rows, SW128.
__device__ __forceinline__ void gemm64(unsigned abase, unsigned bbase, int lane,
                                       int wr, int wc, float (&acc)[2][4][4]) {
    const unsigned sw = (unsigned)(lane & 7) << 4;
    const unsigned arow = (unsigned)(wr * 32 + (lane & 7) + ((lane >> 3) & 1) * 8);
    const unsigned ac16 = (unsigned)((lane >> 4) << 4);
    const unsigned brow = (unsigned)(wc * 32 + (lane & 7));
    const unsigned bc16 = (unsigned)(((lane >> 3) & 1) << 4);
#pragma unroll
    for (int ks = 0; ks < 4; ks++) {
        unsigned acol = ((unsigned)(ks * 32) + ac16) ^ sw;
        unsigned bcol = ((unsigned)(ks * 32) + bc16) ^ sw;
        unsigned a[2][4];
#pragma unroll
        for (int mt = 0; mt < 2; mt++) {
            unsigned addr = abase + (arow + mt * 16) * 128u + acol;
            asm volatile(
                "ldmatrix.sync.aligned.m8n8.x4.shared.b16 {%0,%1,%2,%3}, [%4];"
                : "=r"(a[mt][0]), "=r"(a[mt][1]), "=r"(a[mt][2]), "=r"(a[mt][3])
                : "r"(addr));
        }
        unsigned b[4][2];
#pragma unroll
        for (int nt = 0; nt < 4; nt++) {
            unsigned addr = bbase + (brow + nt * 8) * 128u + bcol;
            asm volatile(
                "ldmatrix.sync.aligned.m8n8.x2.shared.b16 {%0,%1}, [%2];"
                : "=r"(b[nt][0]), "=r"(b[nt][1]) : "r"(addr));
        }
#pragma unroll
        for (int mt = 0; mt < 2; mt++)
#pragma unroll
            for (int nt = 0; nt < 4; nt++) hmma(acc[mt][nt], a[mt], b[nt]);
    }
}

// ---------------------------------------------------------------------------
// Fused KAN layer on mma.sync: acc[128x64] (regs, fp32) accumulates
//   X@W^T (bf16 hi/lo split, 3 GEMMs) + sum_f basis_f @ coef_f (1 GEMM each).
// Epilogue: SMEM roundtrip -> per-half-row LayerNorm + exact GELU.
// ---------------------------------------------------------------------------
__global__ void __launch_bounds__(NTHREADS, 2) kan_kernel(
    const float* __restrict__ X,
    const float* __restrict__ shift,
    const float* __restrict__ lscale,
    const float* __restrict__ skipW,
    const float* __restrict__ skip_b,
    const float* __restrict__ bias,
    const float* __restrict__ gamma,
    const float* __restrict__ beta,
    const float* __restrict__ knots,
    float* __restrict__ out) {
    extern __shared__ char dynraw[];
    char* dynp = (char*)((((uintptr_t)dynraw) + 1023) & ~(uintptr_t)1023);

    __shared__ float kn[68], rcp6[61 * 6];
    __shared__ float sh_s[64], sc_s[64], cb_s[64], ga_s[64], be_s[64];

    const int tid = threadIdx.x;
    const int lane = tid & 31;
    const int wid = tid >> 5;
    const int wr = wid >> 1, wc = wid & 1;
    const int rgbase = blockIdx.x * ROWS;

    if (tid < 68) kn[tid] = knots[tid];
    if (tid < 64) {
        sh_s[tid] = shift[tid];
        sc_s[tid] = log1pf(__expf(lscale[tid])) + 0.001f;  // softplus + 1e-3
        cb_s[tid] = skip_b[tid] + bias[tid];
        ga_s[tid] = gamma[tid];
        be_s[tid] = beta[tid];
    }
    __syncthreads();
    if (tid < 61) {
        int j = tid + 3;
        rcp6[tid * 6 + 0] = 1.0f / (kn[j + 1] - kn[j]);
        rcp6[tid * 6 + 1] = 1.0f / (kn[j + 1] - kn[j - 1]);
        rcp6[tid * 6 + 2] = 1.0f / (kn[j + 2] - kn[j]);
        rcp6[tid * 6 + 3] = 1.0f / (kn[j + 1] - kn[j - 2]);
        rcp6[tid * 6 + 4] = 1.0f / (kn[j + 2] - kn[j - 1]);
        rcp6[tid * 6 + 5] = 1.0f / (kn[j + 3] - kn[j]);
    }

    const int row = tid;                       // row owner (tid < 128)
    const unsigned rx = (unsigned)(row & 7) << 4;

    // ---- stage X hi/lo tiles (A layout, SW128) into the A region ----
    if (tid < 128) {
        const float4* xr4 = reinterpret_cast<const float4*>(X + (size_t)(rgbase + row) * NF);
        char* xhb = dynp + OF_A0 + row * 128;
        char* xlb = dynp + OF_A1 + row * 128;
#pragma unroll 4
        for (int q = 0; q < 16; q++) {
            float4 v = xr4[q];
            float hx = bfround(v.x), hy = bfround(v.y);
            float hz = bfround(v.z), hw = bfround(v.w);
            unsigned h0 = (unsigned)bfbits(hx) | ((unsigned)bfbits(hy) << 16);
            unsigned h1 = (unsigned)bfbits(hz) | ((unsigned)bfbits(hw) << 16);
            unsigned l0 = (unsigned)bfbits(v.x - hx) | ((unsigned)bfbits(v.y - hy) << 16);
            unsigned l1 = (unsigned)bfbits(v.z - hz) | ((unsigned)bfbits(v.w - hw) << 16);
            unsigned o0 = (unsigned)(8 * q) ^ rx;
            unsigned o1 = (unsigned)(8 * q + 4) ^ rx;
            *(unsigned*)(xhb + o0) = h0;
            *(unsigned*)(xhb + o1) = h1;
            *(unsigned*)(xlb + o0) = l0;
            *(unsigned*)(xlb + o1) = l1;
        }
    }
    // ---- stage skip_W hi/lo (B layout [w][f], SW128) ----
    for (int idx = tid; idx < 4096; idx += NTHREADS) {
        int w = idx >> 6, fcol = idx & 63;
        float v = skipW[idx];               // skip_W is [W][F] row-major
        float h = bfround(v);
        unsigned o = (unsigned)w * 128u + ((2u * (unsigned)fcol) ^ (((unsigned)w & 7u) << 4));
        *(unsigned short*)(dynp + OF_WHI + o) = bfbits(h);
        *(unsigned short*)(dynp + OF_WLO + o) = bfbits(v - h);
    }

    // ---- coef prefetch: groups for f=0, f=1 ----
    cpa_coef(dynp, 0, 0, tid);
    asm volatile("cp.async.commit_group;");
    cpa_coef(dynp, 1, 1, tid);
    asm volatile("cp.async.commit_group;");

    __syncthreads();

    float acc[2][4][4];
#pragma unroll
    for (int mt = 0; mt < 2; mt++)
#pragma unroll
        for (int nt = 0; nt < 4; nt++)
#pragma unroll
            for (int e = 0; e < 4; e++) acc[mt][nt][e] = 0.f;

    // ---- skip GEMM: Xhi@Whi + Xhi@Wlo + Xlo@Whi ----
    gemm64(su(dynp + OF_A0), su(dynp + OF_WHI), lane, wr, wc, acc);
    gemm64(su(dynp + OF_A0), su(dynp + OF_WLO), lane, wr, wc, acc);
    gemm64(su(dynp + OF_A1), su(dynp + OF_WHI), lane, wr, wc, acc);
    __syncthreads();  // all X reads done before reuse as basis tiles

    // zero both basis buffers (32KB)
    {
        uint4 z = {0, 0, 0, 0};
        uint4* a0 = reinterpret_cast<uint4*>(dynp + OF_A0);
        for (int i = tid; i < 2048; i += NTHREADS) a0[i] = z;
    }
    __syncthreads();

    int pj0 = -1, pj1 = -1;
    const float* xcol = X + (size_t)(rgbase + row) * NF;

    // basis writer lambda-ish macro: computes feature fb into buffer buf
#define WRITE_BASIS(fb, buf)                                                    \
    do {                                                                        \
        char* Ab = dynp + ((buf) ? OF_A1 : OF_A0) + row * 128;                  \
        int pj = (buf) ? pj1 : pj0;                                             \
        if (pj >= 0) {                                                          \
            _Pragma("unroll") for (int k = 0; k < 4; k++)                       \
                *(unsigned short*)(Ab + ((2u * (unsigned)(pj + k)) ^ rx)) = 0;  \
        }                                                                       \
        float xv = __ldg(xcol + (fb));                                          \
        float arg = (xv - sh_s[fb]) * sc_s[fb];                                 \
        float xs = __fdividef(1.0f, 1.0f + __expf(-arg));                       \
        int jj = (int)(xs * 61.0f);                                             \
        jj = jj < 60 ? jj : 60;                                                 \
        jj = jj < 0 ? 0 : jj;                                                   \
        const int j = jj + 3;                                                   \
        const float* rc = &rcp6[jj * 6];                                        \
        float l1 = xs - kn[j], l2 = xs - kn[j - 1], l3 = xs - kn[j - 2];        \
        float r1 = kn[j + 1] - xs, r2 = kn[j + 2] - xs, r3 = kn[j + 3] - xs;    \
        float t = rc[0];                                                        \
        float N0 = r1 * t, N1 = l1 * t;                                         \
        t = N0 * rc[1]; N0 = r1 * t; float sv = l2 * t;                         \
        t = N1 * rc[2]; N1 = sv + r2 * t; float N2 = l1 * t;                    \
        t = N0 * rc[3]; N0 = r1 * t; sv = l3 * t;                               \
        t = N1 * rc[4]; N1 = sv + r2 * t; sv = l2 * t;                          \
        t = N2 * rc[5]; N2 = sv + r3 * t; float N3 = l1 * t;                    \
        *(unsigned short*)(Ab + ((2u * (unsigned)(jj + 0)) ^ rx)) = bfbits(N0); \
        *(unsigned short*)(Ab + ((2u * (unsigned)(jj + 1)) ^ rx)) = bfbits(N1); \
        *(unsigned short*)(Ab + ((2u * (unsigned)(jj + 2)) ^ rx)) = bfbits(N2); \
        *(unsigned short*)(Ab + ((2u * (unsigned)(jj + 3)) ^ rx)) = bfbits(N3); \
        if (buf) pj1 = jj; else pj0 = jj;                                       \
    } while (0)

    if (tid < 128) WRITE_BASIS(0, 0);   // prologue: basis f=0 into buf0

    for (int f = 0; f < NF; f++) {
        if (f + 2 < NF) cpa_coef(dynp, (f + 2) & 3, f + 2, tid);
        asm volatile("cp.async.commit_group;");
        asm volatile("cp.async.wait_group 2;");   // coef tile f resident

        if (tid < 128 && f + 1 < NF) WRITE_BASIS(f + 1, (f + 1) & 1);

        __syncthreads();  // basis f + coef f visible to all

        unsigned ab = su(dynp + ((f & 1) ? OF_A1 : OF_A0));
        gemm64(ab, su(dynp + OF_C(f & 3)), lane, wr, wc, acc);

        __syncthreads();  // reads of basis buffer done before next overwrite
    }

    // ---- epilogue: accs -> SMEM D (stride-65 f32), LN + GELU ----
    {
        float* D = (float*)(dynp + OF_D);
        int g = lane >> 2, t2 = (lane & 3) * 2;
#pragma unroll
        for (int mt = 0; mt < 2; mt++)
#pragma unroll
            for (int nt = 0; nt < 4; nt++) {
                int r0 = wr * 32 + mt * 16 + g;
                int c0 = wc * 32 + nt * 8 + t2;
                D[r0 * DSTRIDE + c0]           = acc[mt][nt][0];
                D[r0 * DSTRIDE + c0 + 1]       = acc[mt][nt][1];
                D[(r0 + 8) * DSTRIDE + c0]     = acc[mt][nt][2];
                D[(r0 + 8) * DSTRIDE + c0 + 1] = acc[mt][nt][3];
            }
    }
    __syncthreads();

    {
        const int r = tid >> 1, half = tid & 1, cb = half * 32;
        const float* Dp = (float*)(dynp + OF_D) + r * DSTRIDE + cb;
        float y[32];
        float s = 0.f, sq = 0.f;
#pragma unroll
        for (int c = 0; c < 32; c++) {
            float v = Dp[c] + cb_s[cb + c];
            y[c] = v;
            s += v;
            sq += v * v;
        }
        s += __shfl_xor_sync(0xffffffffu, s, 1);
        sq += __shfl_xor_sync(0xffffffffu, sq, 1);
        float mean = s * (1.0f / 64.0f);
        float var = sq * (1.0f / 64.0f) - mean * mean;
        var = fmaxf(var, 0.0f);
        float inv = rsqrtf(var + 1e-5f);

        float4* og = reinterpret_cast<float4*>(out + (size_t)(rgbase + r) * NW + cb);
#pragma unroll
        for (int q = 0; q < 8; q++) {
            float z0 = (y[4 * q + 0] - mean) * inv * ga_s[cb + 4 * q + 0] + be_s[cb + 4 * q + 0];
            float z1 = (y[4 * q + 1] - mean) * inv * ga_s[cb + 4 * q + 1] + be_s[cb + 4 * q + 1];
            float z2 = (y[4 * q + 2] - mean) * inv * ga_s[cb + 4 * q + 2] + be_s[cb + 4 * q + 2];
            float z3 = (y[4 * q + 3] - mean) * inv * ga_s[cb + 4 * q + 3] + be_s[cb + 4 * q + 3];
            float4 o;
            o.x = 0.5f * z0 * (1.0f + erff(z0 * 0.70710678118654752f));
            o.y = 0.5f * z1 * (1.0f + erff(z1 * 0.70710678118654752f));
            o.z = 0.5f * z2 * (1.0f + erff(z2 * 0.70710678118654752f));
            o.w = 0.5f * z3 * (1.0f + erff(z3 * 0.70710678118654752f));
            og[q] = o;
        }
    }
}

extern "C" void kernel_launch(void* const* d_in, const int* in_sizes, int n_in,
                              void* d_out, int out_size) {
    const float* X      = (const float*)d_in[0];
    const float* shift  = (const float*)d_in[1];
    const float* lscale = (const float*)d_in[2];
    const float* coef   = (const float*)d_in[3];
    const float* skipW  = (const float*)d_in[4];
    const float* skipb  = (const float*)d_in[5];
    const float* bias   = (const float*)d_in[6];
    const float* gam    = (const float*)d_in[7];
    const float* bet    = (const float*)d_in[8];
    const float* knots  = (const float*)d_in[9];

    cudaFuncSetAttribute(kan_kernel, cudaFuncAttributeMaxDynamicSharedMemorySize,
                         DYN_BYTES);

    prep_kernel<<<256, 256>>>(coef);
    kan_kernel<<<NCTA, NTHREADS, DYN_BYTES>>>(X, shift, lscale, skipW, skipb,
                                              bias, gam, bet, knots,
                                              (float*)d_out);
}

// round 5
// speedup vs baseline: 1.4253x; 1.0325x over previous
#include <cuda_runtime.h>
#include <cuda_bf16.h>
#include <cstdint>

#define NF 64
#define NW 64
#define NBATCH 32768
#define ROWS 256
#define NCTA (NBATCH / ROWS)
#define NTHREADS 256

// ---------------- dynamic SMEM layout (offsets from 1024-aligned base) ------
// A region doubles as X hi/lo staging (prologue) then basis double buffer,
// then (with W region) as the f32 D matrix in the epilogue.
#define OF_A0   0
#define OF_A1   32768
#define OF_WHI  65536
#define OF_WLO  73728
#define OF_C(s) (81920 + (s) * 8192)    // coef ring, 4 slots, through 114688
#define OF_D    0                        // f32 D[256][65] overlay (epilogue only)
#define DSTRIDE 65
#define DYN_BYTES (114688 + 1024)

// ---------------- device globals (allocation-free scratch) ------------------
__device__ __align__(16) unsigned short g_coefB[NF * 64 * 64];  // bf16, pre-swizzled [f][w][g]

__device__ __forceinline__ unsigned su(const void* p) {
    return (unsigned)__cvta_generic_to_shared(p);
}
__device__ __forceinline__ unsigned short bfbits(float x) {
    __nv_bfloat16 h = __float2bfloat16(x);
    return *reinterpret_cast<unsigned short*>(&h);
}
__device__ __forceinline__ float bfround(float x) {
    return __bfloat162float(__float2bfloat16(x));
}

// ---------------------------------------------------------------------------
// Prep: spline_coeffs [f][g][w] fp32 -> bf16 B-tiles [f][w-row][g-col],
// SW128 pre-swizzled so a linear cp.async lands them ldmatrix-ready.
// ---------------------------------------------------------------------------
__global__ void prep_kernel(const float* __restrict__ coef) {
    int i0 = blockIdx.x * blockDim.x + threadIdx.x;
    int stride = gridDim.x * blockDim.x;
    for (int i = i0; i < NF * 64 * 64; i += stride) {
        int f = i >> 12, rem = i & 4095, g = rem >> 6, w = rem & 63;
        unsigned o = (unsigned)w * 128u + ((2u * (unsigned)g) ^ (((unsigned)w & 7u) << 4));
        g_coefB[(f << 12) + (o >> 1)] = bfbits(coef[i]);
    }
}

// 8KB coef tile f -> SMEM slot via cp.async (2 x 16B per thread)
__device__ __forceinline__ void cpa_coef(char* dynp, int slot, int f, int tid) {
    unsigned dst = su(dynp + OF_C(slot)) + tid * 16;
    const char* src = (const char*)(g_coefB + ((size_t)f << 12)) + tid * 16;
    asm volatile(
        "cp.async.cg.shared.global [%0], [%1], 16;\n\t"
        "cp.async.cg.shared.global [%2], [%3], 16;"
        :: "r"(dst), "l"(src), "r"(dst + 4096), "l"(src + 4096) : "memory");
}

__device__ __forceinline__ void hmma(float (&c)[4], const unsigned (&a)[4],
                                     const unsigned (&b)[2]) {
    asm volatile(
        "mma.sync.aligned.m16n8k16.row.col.f32.bf16.bf16.f32 "
        "{%0,%1,%2,%3}, {%4,%5,%6,%7}, {%8,%9}, {%0,%1,%2,%3};"
        : "+f"(c[0]), "+f"(c[1]), "+f"(c[2]), "+f"(c[3])
        : "r"(a[0]), "r"(a[1]), "r"(a[2]), "r"(a[3]), "r"(b[0]), "r"(b[1]));
}

// One 256x64 @ 64x64 -> 256x64 GEMM step for this warp (warp tile 64x32).
// A tile: [row][k] bf16, 128B rows, SW128.  B tile: [n][k] bf16, 128B rows, SW128.
__device__ __forceinline__ void gemm64(unsigned abase, unsigned bbase, int lane,
                                       int wr, int wc, float (&acc)[4][4][4]) {
    const unsigned sw = (unsigned)(lane & 7) << 4;
    const unsigned arow = (unsigned)(wr * 64 + (lane & 7) + ((lane >> 3) & 1) * 8);
    const unsigned ac16 = (unsigned)((lane >> 4) << 4);
    const unsigned brow = (unsigned)(wc * 32 + (lane & 7));
    const unsigned bc16 = (unsigned)(((lane >> 3) & 1) << 4);
#pragma unroll
    for (int ks = 0; ks < 4; ks++) {
        unsigned acol = ((unsigned)(ks * 32) + ac16) ^ sw;
        unsigned bcol = ((unsigned)(ks * 32) + bc16) ^ sw;
        unsigned b[4][2];
#pragma unroll
        for (int nt = 0; nt < 4; nt++) {
            unsigned addr = bbase + (brow + nt * 8) * 128u + bcol;
            asm volatile(
                "ldmatrix.sync.aligned.m8n8.x2.shared.b16 {%0,%1}, [%2];"
                : "=r"(b[nt][0]), "=r"(b[nt][1]) : "r"(addr));
        }
#pragma unroll
        for (int mt = 0; mt < 4; mt++) {
            unsigned a[4];
            unsigned addr = abase + (arow + mt * 16) * 128u + acol;
            asm volatile(
                "ldmatrix.sync.aligned.m8n8.x4.shared.b16 {%0,%1,%2,%3}, [%4];"
                : "=r"(a[0]), "=r"(a[1]), "=r"(a[2]), "=r"(a[3]) : "r"(addr));
#pragma unroll
            for (int nt = 0; nt < 4; nt++) hmma(acc[mt][nt], a, b[nt]);
        }
    }
}

// ---------------------------------------------------------------------------
// Fused KAN layer on mma.sync: acc[256x64] (regs, fp32) accumulates
//   X@W^T (bf16 hi/lo split, 3 GEMMs) + sum_f basis_f @ coef_f (1 GEMM each).
// One wave: 128 CTAs, 256 rows each, every thread owns one basis row.
// ---------------------------------------------------------------------------
__global__ void __launch_bounds__(NTHREADS, 1) kan_kernel(
    const float* __restrict__ X,
    const float* __restrict__ shift,
    const float* __restrict__ lscale,
    const float* __restrict__ skipW,
    const float* __restrict__ skip_b,
    const float* __restrict__ bias,
    const float* __restrict__ gamma,
    const float* __restrict__ beta,
    const float* __restrict__ knots,
    float* __restrict__ out) {
    extern __shared__ char dynraw[];
    char* dynp = (char*)((((uintptr_t)dynraw) + 1023) & ~(uintptr_t)1023);

    __shared__ float kn[68], rcp6[61 * 6];
    __shared__ float sh_s[64], sc_s[64], cb_s[64], ga_s[64], be_s[64];

    const int tid = threadIdx.x;
    const int lane = tid & 31;
    const int wid = tid >> 5;
    const int wr = wid >> 1, wc = wid & 1;
    const int rgbase = blockIdx.x * ROWS;

    if (tid < 68) kn[tid] = knots[tid];
    if (tid < 64) {
        sh_s[tid] = shift[tid];
        sc_s[tid] = log1pf(__expf(lscale[tid])) + 0.001f;  // softplus + 1e-3
        cb_s[tid] = skip_b[tid] + bias[tid];
        ga_s[tid] = gamma[tid];
        be_s[tid] = beta[tid];
    }
    __syncthreads();
    if (tid < 61) {
        int j = tid + 3;
        rcp6[tid * 6 + 0] = 1.0f / (kn[j + 1] - kn[j]);
        rcp6[tid * 6 + 1] = 1.0f / (kn[j + 1] - kn[j - 1]);
        rcp6[tid * 6 + 2] = 1.0f / (kn[j + 2] - kn[j]);
        rcp6[tid * 6 + 3] = 1.0f / (kn[j + 1] - kn[j - 2]);
        rcp6[tid * 6 + 4] = 1.0f / (kn[j + 2] - kn[j - 1]);
        rcp6[tid * 6 + 5] = 1.0f / (kn[j + 3] - kn[j]);
    }

    const int row = tid;                       // every thread owns one row
    const unsigned rx = (unsigned)(row & 7) << 4;

    // ---- stage X hi/lo tiles (A layout, SW128) into the A region ----
    {
        const float4* xr4 = reinterpret_cast<const float4*>(X + (size_t)(rgbase + row) * NF);
        char* xhb = dynp + OF_A0 + row * 128;
        char* xlb = dynp + OF_A1 + row * 128;
#pragma unroll 4
        for (int q = 0; q < 16; q++) {
            float4 v = xr4[q];
            float hx = bfround(v.x), hy = bfround(v.y);
            float hz = bfround(v.z), hw = bfround(v.w);
            unsigned h0 = (unsigned)bfbits(hx) | ((unsigned)bfbits(hy) << 16);
            unsigned h1 = (unsigned)bfbits(hz) | ((unsigned)bfbits(hw) << 16);
            unsigned l0 = (unsigned)bfbits(v.x - hx) | ((unsigned)bfbits(v.y - hy) << 16);
            unsigned l1 = (unsigned)bfbits(v.z - hz) | ((unsigned)bfbits(v.w - hw) << 16);
            unsigned o0 = (unsigned)(8 * q) ^ rx;
            unsigned o1 = (unsigned)(8 * q + 4) ^ rx;
            *(unsigned*)(xhb + o0) = h0;
            *(unsigned*)(xhb + o1) = h1;
            *(unsigned*)(xlb + o0) = l0;
            *(unsigned*)(xlb + o1) = l1;
        }
    }
    // ---- stage skip_W hi/lo (B layout [w][f], SW128) ----
    for (int idx = tid; idx < 4096; idx += NTHREADS) {
        int w = idx >> 6, fcol = idx & 63;
        float v = skipW[idx];               // skip_W is [W][F] row-major
        float h = bfround(v);
        unsigned o = (unsigned)w * 128u + ((2u * (unsigned)fcol) ^ (((unsigned)w & 7u) << 4));
        *(unsigned short*)(dynp + OF_WHI + o) = bfbits(h);
        *(unsigned short*)(dynp + OF_WLO + o) = bfbits(v - h);
    }

    // ---- coef prefetch: groups for f=0, f=1 ----
    cpa_coef(dynp, 0, 0, tid);
    asm volatile("cp.async.commit_group;");
    cpa_coef(dynp, 1, 1, tid);
    asm volatile("cp.async.commit_group;");

    __syncthreads();

    float acc[4][4][4];
#pragma unroll
    for (int mt = 0; mt < 4; mt++)
#pragma unroll
        for (int nt = 0; nt < 4; nt++)
#pragma unroll
            for (int e = 0; e < 4; e++) acc[mt][nt][e] = 0.f;

    // ---- skip GEMM: Xhi@Whi + Xhi@Wlo + Xlo@Whi ----
    gemm64(su(dynp + OF_A0), su(dynp + OF_WHI), lane, wr, wc, acc);
    gemm64(su(dynp + OF_A0), su(dynp + OF_WLO), lane, wr, wc, acc);
    gemm64(su(dynp + OF_A1), su(dynp + OF_WHI), lane, wr, wc, acc);
    __syncthreads();  // all X reads done before reuse as basis tiles

    // zero both basis buffers (64KB)
    {
        uint4 z = {0, 0, 0, 0};
        uint4* a0 = reinterpret_cast<uint4*>(dynp + OF_A0);
        for (int i = tid; i < 4096; i += NTHREADS) a0[i] = z;
    }
    __syncthreads();

    int pw0 = -1, pw1 = -1;  // previous 3-word window byte base per buffer
    const float* xcol = X + (size_t)(rgbase + row) * NF;

    // Basis writer: 4 nonzeros packed into a word-aligned 3-u32 window
    // (zeros in slack slots are correct; previous window cleared first).
#define WRITE_BASIS(fb, buf)                                                   \
    do {                                                                       \
        char* Ab = dynp + ((buf) ? OF_A1 : OF_A0) + row * 128;                 \
        int pw = (buf) ? pw1 : pw0;                                            \
        if (pw >= 0) {                                                         \
            *(unsigned*)(Ab + ((unsigned)(pw + 0) ^ rx)) = 0;                  \
            *(unsigned*)(Ab + ((unsigned)(pw + 4) ^ rx)) = 0;                  \
            if (pw + 8 < 128) *(unsigned*)(Ab + ((unsigned)(pw + 8) ^ rx)) = 0;\
        }                                                                      \
        float xv = __ldg(xcol + (fb));                                         \
        float arg = (xv - sh_s[fb]) * sc_s[fb];                                \
        float xs = __fdividef(1.0f, 1.0f + __expf(-arg));                      \
        int jj = (int)(xs * 61.0f);                                            \
        jj = jj < 60 ? jj : 60;                                                \
        jj = jj < 0 ? 0 : jj;                                                  \
        const int j = jj + 3;                                                  \
        const float* rc = &rcp6[jj * 6];                                       \
        float l1 = xs - kn[j], l2 = xs - kn[j - 1], l3 = xs - kn[j - 2];       \
        float r1 = kn[j + 1] - xs, r2 = kn[j + 2] - xs, r3 = kn[j + 3] - xs;   \
        float t = rc[0];                                                       \
        float N0 = r1 * t, N1 = l1 * t;                                        \
        t = N0 * rc[1]; N0 = r1 * t; float sv = l2 * t;                        \
        t = N1 * rc[2]; N1 = sv + r2 * t; float N2 = l1 * t;                   \
        t = N0 * rc[3]; N0 = r1 * t; sv = l3 * t;                              \
        t = N1 * rc[4]; N1 = sv + r2 * t; sv = l2 * t;                         \
        t = N2 * rc[5]; N2 = sv + r3 * t; float N3 = l1 * t;                   \
        unsigned b0 = bfbits(N0), b1 = bfbits(N1);                             \
        unsigned b2 = bfbits(N2), b3 = bfbits(N3);                             \
        int wb = (jj >> 1) * 4;                                                \
        unsigned w0, w1, w2;                                                   \
        if (jj & 1) { w0 = b0 << 16; w1 = b1 | (b2 << 16); w2 = b3; }          \
        else        { w0 = b0 | (b1 << 16); w1 = b2 | (b3 << 16); w2 = 0; }    \
        *(unsigned*)(Ab + ((unsigned)(wb + 0) ^ rx)) = w0;                     \
        *(unsigned*)(Ab + ((unsigned)(wb + 4) ^ rx)) = w1;                     \
        if (wb + 8 < 128) *(unsigned*)(Ab + ((unsigned)(wb + 8) ^ rx)) = w2;   \
        if (buf) pw1 = wb; else pw0 = wb;                                      \
    } while (0)

    WRITE_BASIS(0, 0);   // prologue: basis f=0 into buf0

    for (int f = 0; f < NF; f++) {
        if (f + 2 < NF) cpa_coef(dynp, (f + 2) & 3, f + 2, tid);
        asm volatile("cp.async.commit_group;");
        asm volatile("cp.async.wait_group 2;");   // coef tile f resident

        if (f + 1 < NF) WRITE_BASIS(f + 1, (f + 1) & 1);

        __syncthreads();  // basis f + coef f visible to all

        unsigned ab = su(dynp + ((f & 1) ? OF_A1 : OF_A0));
        gemm64(ab, su(dynp + OF_C(f & 3)), lane, wr, wc, acc);

        __syncthreads();  // reads of basis buffer done before next overwrite
    }

    // ---- epilogue: accs -> SMEM D (stride-65 f32), per-thread LN + GELU ----
    {
        float* D = (float*)(dynp + OF_D);
        int g = lane >> 2, t2 = (lane & 3) * 2;
#pragma unroll
        for (int mt = 0; mt < 4; mt++)
#pragma unroll
            for (int nt = 0; nt < 4; nt++) {
                int r0 = wr * 64 + mt * 16 + g;
                int c0 = wc * 32 + nt * 8 + t2;
                D[r0 * DSTRIDE + c0]           = acc[mt][nt][0];
                D[r0 * DSTRIDE + c0 + 1]       = acc[mt][nt][1];
                D[(r0 + 8) * DSTRIDE + c0]     = acc[mt][nt][2];
                D[(r0 + 8) * DSTRIDE + c0 + 1] = acc[mt][nt][3];
            }
    }
    __syncthreads();

    {
        const float* Dp = (float*)(dynp + OF_D) + row * DSTRIDE;
        float y[64];
        float s = 0.f, sq = 0.f;
#pragma unroll
        for (int c = 0; c < 64; c++) {
            float v = Dp[c] + cb_s[c];
            y[c] = v;
            s += v;
            sq += v * v;
        }
        float mean = s * (1.0f / 64.0f);
        float var = sq * (1.0f / 64.0f) - mean * mean;
        var = fmaxf(var, 0.0f);
        float inv = rsqrtf(var + 1e-5f);

        float4* og = reinterpret_cast<float4*>(out + (size_t)(rgbase + row) * NW);
#pragma unroll
        for (int q = 0; q < 16; q++) {
            float z0 = (y[4 * q + 0] - mean) * inv * ga_s[4 * q + 0] + be_s[4 * q + 0];
            float z1 = (y[4 * q + 1] - mean) * inv * ga_s[4 * q + 1] + be_s[4 * q + 1];
            float z2 = (y[4 * q + 2] - mean) * inv * ga_s[4 * q + 2] + be_s[4 * q + 2];
            float z3 = (y[4 * q + 3] - mean) * inv * ga_s[4 * q + 3] + be_s[4 * q + 3];
            float4 o;
            o.x = 0.5f * z0 * (1.0f + erff(z0 * 0.70710678118654752f));
            o.y = 0.5f * z1 * (1.0f + erff(z1 * 0.70710678118654752f));
            o.z = 0.5f * z2 * (1.0f + erff(z2 * 0.70710678118654752f));
            o.w = 0.5f * z3 * (1.0f + erff(z3 * 0.70710678118654752f));
            og[q] = o;
        }
    }
}

extern "C" void kernel_launch(void* const* d_in, const int* in_sizes, int n_in,
                              void* d_out, int out_size) {
    const float* X      = (const float*)d_in[0];
    const float* shift  = (const float*)d_in[1];
    const float* lscale = (const float*)d_in[2];
    const float* coef   = (const float*)d_in[3];
    const float* skipW  = (const float*)d_in[4];
    const float* skipb  = (const float*)d_in[5];
    const float* bias   = (const float*)d_in[6];
    const float* gam    = (const float*)d_in[7];
    const float* bet    = (const float*)d_in[8];
    const float* knots  = (const float*)d_in[9];

    cudaFuncSetAttribute(kan_kernel, cudaFuncAttributeMaxDynamicSharedMemorySize,
                         DYN_BYTES);

    prep_kernel<<<256, 256>>>(coef);
    kan_kernel<<<NCTA, NTHREADS, DYN_BYTES>>>(X, shift, lscale, skipW, skipb,
                                              bias, gam, bet, knots,
                                              (float*)d_out);
}

// round 6
// speedup vs baseline: 1.4385x; 1.0092x over previous
#include <cuda_runtime.h>
#include <cuda_bf16.h>
#include <cstdint>

#define NF 64
#define NW 64
#define NBATCH 32768
#define ROWS 256
#define NCTA (NBATCH / ROWS)
#define NTHREADS 256

// ---------------- dynamic SMEM layout (offsets from 1024-aligned base) ------
// 4 basis buffers (bufs 0/1 double as X hi/lo staging in the prologue, and
// the region doubles as the f32 D matrix in the epilogue).
#define OF_A(b) ((b) * 32768)                 // 4 x 32KB basis tiles, SW128
#define OF_C(s) (131072 + (s) * 8192)         // coef ring, 6 slots (48KB)
#define OF_WHI  180224
#define OF_WLO  188416
#define OF_D    0                              // f32 D[256][65] overlay (epilogue)
#define DSTRIDE 65
#define DYN_BYTES (196608 + 1024)

// ---------------- device globals (allocation-free scratch) ------------------
__device__ __align__(16) unsigned short g_coefB[NF * 64 * 64];  // bf16, pre-swizzled [f][w][g]

__device__ __forceinline__ unsigned su(const void* p) {
    return (unsigned)__cvta_generic_to_shared(p);
}
__device__ __forceinline__ unsigned short bfbits(float x) {
    __nv_bfloat16 h = __float2bfloat16(x);
    return *reinterpret_cast<unsigned short*>(&h);
}
__device__ __forceinline__ float bfround(float x) {
    return __bfloat162float(__float2bfloat16(x));
}

// ---------------------------------------------------------------------------
// Prep: spline_coeffs [f][g][w] fp32 -> bf16 B-tiles [f][w-row][g-col],
// SW128 pre-swizzled so a linear cp.async lands them ldmatrix-ready.
// ---------------------------------------------------------------------------
__global__ void prep_kernel(const float* __restrict__ coef) {
    int i0 = blockIdx.x * blockDim.x + threadIdx.x;
    int stride = gridDim.x * blockDim.x;
    for (int i = i0; i < NF * 64 * 64; i += stride) {
        int f = i >> 12, rem = i & 4095, g = rem >> 6, w = rem & 63;
        unsigned o = (unsigned)w * 128u + ((2u * (unsigned)g) ^ (((unsigned)w & 7u) << 4));
        g_coefB[(f << 12) + (o >> 1)] = bfbits(coef[i]);
    }
}

// 8KB coef tile f -> SMEM slot via cp.async (2 x 16B per thread)
__device__ __forceinline__ void cpa_coef(char* dynp, int slot, int f, int tid) {
    unsigned dst = su(dynp + OF_C(slot)) + tid * 16;
    const char* src = (const char*)(g_coefB + ((size_t)f << 12)) + tid * 16;
    asm volatile(
        "cp.async.cg.shared.global [%0], [%1], 16;\n\t"
        "cp.async.cg.shared.global [%2], [%3], 16;"
        :: "r"(dst), "l"(src), "r"(dst + 4096), "l"(src + 4096) : "memory");
}

__device__ __forceinline__ void hmma(float (&c)[4], const unsigned (&a)[4],
                                     const unsigned (&b)[2]) {
    asm volatile(
        "mma.sync.aligned.m16n8k16.row.col.f32.bf16.bf16.f32 "
        "{%0,%1,%2,%3}, {%4,%5,%6,%7}, {%8,%9}, {%0,%1,%2,%3};"
        : "+f"(c[0]), "+f"(c[1]), "+f"(c[2]), "+f"(c[3])
        : "r"(a[0]), "r"(a[1]), "r"(a[2]), "r"(a[3]), "r"(b[0]), "r"(b[1]));
}

// One 256x64 @ 64x64 -> 256x64 GEMM step for this warp (warp tile 64x32).
// A tile: [row][k] bf16, 128B rows, SW128.  B tile: [n][k] bf16, 128B rows, SW128.
__device__ __forceinline__ void gemm64(unsigned abase, unsigned bbase, int lane,
                                       int wr, int wc, float (&acc)[4][4][4]) {
    const unsigned sw = (unsigned)(lane & 7) << 4;
    const unsigned arow = (unsigned)(wr * 64 + (lane & 7) + ((lane >> 3) & 1) * 8);
    const unsigned ac16 = (unsigned)((lane >> 4) << 4);
    const unsigned brow = (unsigned)(wc * 32 + (lane & 7));
    const unsigned bc16 = (unsigned)(((lane >> 3) & 1) << 4);
#pragma unroll
    for (int ks = 0; ks < 4; ks++) {
        unsigned acol = ((unsigned)(ks * 32) + ac16) ^ sw;
        unsigned bcol = ((unsigned)(ks * 32) + bc16) ^ sw;
        unsigned b[4][2];
#pragma unroll
        for (int nt = 0; nt < 4; nt++) {
            unsigned addr = bbase + (brow + nt * 8) * 128u + bcol;
            asm volatile(
                "ldmatrix.sync.aligned.m8n8.x2.shared.b16 {%0,%1}, [%2];"
                : "=r"(b[nt][0]), "=r"(b[nt][1]) : "r"(addr));
        }
#pragma unroll
        for (int mt = 0; mt < 4; mt++) {
            unsigned a[4];
            unsigned addr = abase + (arow + mt * 16) * 128u + acol;
            asm volatile(
                "ldmatrix.sync.aligned.m8n8.x4.shared.b16 {%0,%1,%2,%3}, [%4];"
                : "=r"(a[0]), "=r"(a[1]), "=r"(a[2]), "=r"(a[3]) : "r"(addr));
#pragma unroll
            for (int nt = 0; nt < 4; nt++) hmma(acc[mt][nt], a, b[nt]);
        }
    }
}

// Basis writer: 4 cubic B-spline nonzeros packed into a word-aligned 3-u32
// window (slack slots are true zeros); clears this buffer's previous window.
__device__ __forceinline__ void write_basis(char* Ab, unsigned rx,
                                            const float* xcol, int fb,
                                            const float* sh_s, const float* sc_s,
                                            const float* kn, const float* rcp6,
                                            int& pw) {
    if (pw >= 0) {
        *(unsigned*)(Ab + ((unsigned)(pw + 0) ^ rx)) = 0;
        *(unsigned*)(Ab + ((unsigned)(pw + 4) ^ rx)) = 0;
        if (pw + 8 < 128) *(unsigned*)(Ab + ((unsigned)(pw + 8) ^ rx)) = 0;
    }
    float xv = __ldg(xcol + fb);
    float arg = (xv - sh_s[fb]) * sc_s[fb];
    float xs = __fdividef(1.0f, 1.0f + __expf(-arg));
    int jj = (int)(xs * 61.0f);
    jj = jj < 60 ? jj : 60;
    jj = jj < 0 ? 0 : jj;
    const int j = jj + 3;
    const float* rc = &rcp6[jj * 6];
    float l1 = xs - kn[j], l2 = xs - kn[j - 1], l3 = xs - kn[j - 2];
    float r1 = kn[j + 1] - xs, r2 = kn[j + 2] - xs, r3 = kn[j + 3] - xs;
    float t = rc[0];
    float N0 = r1 * t, N1 = l1 * t;
    t = N0 * rc[1]; N0 = r1 * t; float sv = l2 * t;
    t = N1 * rc[2]; N1 = sv + r2 * t; float N2 = l1 * t;
    t = N0 * rc[3]; N0 = r1 * t; sv = l3 * t;
    t = N1 * rc[4]; N1 = sv + r2 * t; sv = l2 * t;
    t = N2 * rc[5]; N2 = sv + r3 * t; float N3 = l1 * t;
    unsigned b0 = bfbits(N0), b1 = bfbits(N1);
    unsigned b2 = bfbits(N2), b3 = bfbits(N3);
    int wb = (jj >> 1) * 4;
    unsigned w0, w1, w2;
    if (jj & 1) { w0 = b0 << 16; w1 = b1 | (b2 << 16); w2 = b3; }
    else        { w0 = b0 | (b1 << 16); w1 = b2 | (b3 << 16); w2 = 0; }
    *(unsigned*)(Ab + ((unsigned)(wb + 0) ^ rx)) = w0;
    *(unsigned*)(Ab + ((unsigned)(wb + 4) ^ rx)) = w1;
    if (wb + 8 < 128) *(unsigned*)(Ab + ((unsigned)(wb + 8) ^ rx)) = w2;
    pw = wb;
}

// ---------------------------------------------------------------------------
// Fused KAN layer on mma.sync, software-pipelined:
//   per iteration (2 features): write basis f+2,f+3 into the idle buffer pair,
//   then GEMM features f,f+1 from the pair written last iteration, then ONE
//   __syncthreads. 4 basis buffers make this safe.
// ---------------------------------------------------------------------------
__global__ void __launch_bounds__(NTHREADS, 1) kan_kernel(
    const float* __restrict__ X,
    const float* __restrict__ shift,
    const float* __restrict__ lscale,
    const float* __restrict__ skipW,
    const float* __restrict__ skip_b,
    const float* __restrict__ bias,
    const float* __restrict__ gamma,
    const float* __restrict__ beta,
    const float* __restrict__ knots,
    float* __restrict__ out) {
    extern __shared__ char dynraw[];
    char* dynp = (char*)((((uintptr_t)dynraw) + 1023) & ~(uintptr_t)1023);

    __shared__ float kn[68], rcp6[61 * 6];
    __shared__ float sh_s[64], sc_s[64], cb_s[64], ga_s[64], be_s[64];

    const int tid = threadIdx.x;
    const int lane = tid & 31;
    const int wid = tid >> 5;
    const int wr = wid >> 1, wc = wid & 1;
    const int rgbase = blockIdx.x * ROWS;

    if (tid < 68) kn[tid] = knots[tid];
    if (tid < 64) {
        sh_s[tid] = shift[tid];
        sc_s[tid] = log1pf(__expf(lscale[tid])) + 0.001f;  // softplus + 1e-3
        cb_s[tid] = skip_b[tid] + bias[tid];
        ga_s[tid] = gamma[tid];
        be_s[tid] = beta[tid];
    }
    __syncthreads();
    if (tid < 61) {
        int j = tid + 3;
        rcp6[tid * 6 + 0] = 1.0f / (kn[j + 1] - kn[j]);
        rcp6[tid * 6 + 1] = 1.0f / (kn[j + 1] - kn[j - 1]);
        rcp6[tid * 6 + 2] = 1.0f / (kn[j + 2] - kn[j]);
        rcp6[tid * 6 + 3] = 1.0f / (kn[j + 1] - kn[j - 2]);
        rcp6[tid * 6 + 4] = 1.0f / (kn[j + 2] - kn[j - 1]);
        rcp6[tid * 6 + 5] = 1.0f / (kn[j + 3] - kn[j]);
    }

    const int row = tid;                       // every thread owns one row
    const unsigned rx = (unsigned)(row & 7) << 4;

    // ---- stage X hi/lo tiles (A layout, SW128) into bufs 0/1 ----
    {
        const float4* xr4 = reinterpret_cast<const float4*>(X + (size_t)(rgbase + row) * NF);
        char* xhb = dynp + OF_A(0) + row * 128;
        char* xlb = dynp + OF_A(1) + row * 128;
#pragma unroll 4
        for (int q = 0; q < 16; q++) {
            float4 v = xr4[q];
            float hx = bfround(v.x), hy = bfround(v.y);
            float hz = bfround(v.z), hw = bfround(v.w);
            unsigned h0 = (unsigned)bfbits(hx) | ((unsigned)bfbits(hy) << 16);
            unsigned h1 = (unsigned)bfbits(hz) | ((unsigned)bfbits(hw) << 16);
            unsigned l0 = (unsigned)bfbits(v.x - hx) | ((unsigned)bfbits(v.y - hy) << 16);
            unsigned l1 = (unsigned)bfbits(v.z - hz) | ((unsigned)bfbits(v.w - hw) << 16);
            unsigned o0 = (unsigned)(8 * q) ^ rx;
            unsigned o1 = (unsigned)(8 * q + 4) ^ rx;
            *(unsigned*)(xhb + o0) = h0;
            *(unsigned*)(xhb + o1) = h1;
            *(unsigned*)(xlb + o0) = l0;
            *(unsigned*)(xlb + o1) = l1;
        }
    }
    // ---- stage skip_W hi/lo (B layout [w][f], SW128) ----
    for (int idx = tid; idx < 4096; idx += NTHREADS) {
        int w = idx >> 6, fcol = idx & 63;
        float v = skipW[idx];               // skip_W is [W][F] row-major
        float h = bfround(v);
        unsigned o = (unsigned)w * 128u + ((2u * (unsigned)fcol) ^ (((unsigned)w & 7u) << 4));
        *(unsigned short*)(dynp + OF_WHI + o) = bfbits(h);
        *(unsigned short*)(dynp + OF_WLO + o) = bfbits(v - h);
    }
    // ---- zero basis bufs 2,3 (not used by skip GEMM) ----
    {
        uint4 z = {0, 0, 0, 0};
        uint4* a2 = reinterpret_cast<uint4*>(dynp + OF_A(2));
        for (int i = tid; i < 4096; i += NTHREADS) a2[i] = z;
    }

    // ---- coef prefetch: pairs (0,1) and (2,3) as two groups ----
    cpa_coef(dynp, 0, 0, tid);
    cpa_coef(dynp, 1, 1, tid);
    asm volatile("cp.async.commit_group;");
    cpa_coef(dynp, 2, 2, tid);
    cpa_coef(dynp, 3, 3, tid);
    asm volatile("cp.async.commit_group;");

    __syncthreads();

    float acc[4][4][4];
#pragma unroll
    for (int mt = 0; mt < 4; mt++)
#pragma unroll
        for (int nt = 0; nt < 4; nt++)
#pragma unroll
            for (int e = 0; e < 4; e++) acc[mt][nt][e] = 0.f;

    // ---- skip GEMM: Xhi@Whi + Xhi@Wlo + Xlo@Whi ----
    gemm64(su(dynp + OF_A(0)), su(dynp + OF_WHI), lane, wr, wc, acc);
    gemm64(su(dynp + OF_A(0)), su(dynp + OF_WLO), lane, wr, wc, acc);
    gemm64(su(dynp + OF_A(1)), su(dynp + OF_WHI), lane, wr, wc, acc);
    __syncthreads();  // all X reads done before reuse as basis tiles

    // zero basis bufs 0,1 (were X staging)
    {
        uint4 z = {0, 0, 0, 0};
        uint4* a0 = reinterpret_cast<uint4*>(dynp + OF_A(0));
        for (int i = tid; i < 4096; i += NTHREADS) a0[i] = z;
    }
    __syncthreads();

    int pw0 = -1, pw1 = -1, pw2 = -1, pw3 = -1;
    const float* xcol = X + (size_t)(rgbase + row) * NF;
    char* Ab0 = dynp + OF_A(0) + row * 128;
    char* Ab1 = dynp + OF_A(1) + row * 128;
    char* Ab2 = dynp + OF_A(2) + row * 128;
    char* Ab3 = dynp + OF_A(3) + row * 128;

    // prologue: basis f=0 -> buf0, f=1 -> buf1
    write_basis(Ab0, rx, xcol, 0, sh_s, sc_s, kn, rcp6, pw0);
    write_basis(Ab1, rx, xcol, 1, sh_s, sc_s, kn, rcp6, pw1);
    __syncthreads();

    int cs = 0;  // coef slot of feature f (ring of 6)
    for (int f = 0; f < NF; f += 2) {
        // prefetch coef pair (f+4, f+5)
        if (f + 4 < NF) {
            int ps = cs + 4 >= 6 ? cs - 2 : cs + 4;  // (cs+4) % 6, cs even
            cpa_coef(dynp, ps, f + 4, tid);
            cpa_coef(dynp, ps + 1, f + 5, tid);
        }
        asm volatile("cp.async.commit_group;");

        // write basis pair (f+2, f+3) into the idle buffer pair
        if (f + 2 < NF) {
            if (f & 2) {
                write_basis(Ab0, rx, xcol, f + 2, sh_s, sc_s, kn, rcp6, pw0);
                write_basis(Ab1, rx, xcol, f + 3, sh_s, sc_s, kn, rcp6, pw1);
            } else {
                write_basis(Ab2, rx, xcol, f + 2, sh_s, sc_s, kn, rcp6, pw2);
                write_basis(Ab3, rx, xcol, f + 3, sh_s, sc_s, kn, rcp6, pw3);
            }
        }

        asm volatile("cp.async.wait_group 2;");   // coef f, f+1 resident

        // GEMM features f, f+1 (basis written last iteration, coef from ring)
        unsigned ab0 = su(dynp + OF_A(0)) + (unsigned)(f & 2) * 32768u;
        gemm64(ab0, su(dynp + OF_C(0)) + (unsigned)cs * 8192u, lane, wr, wc, acc);
        gemm64(ab0 + 32768u, su(dynp + OF_C(0)) + (unsigned)(cs + 1) * 8192u,
               lane, wr, wc, acc);

        cs = cs + 2 >= 6 ? 0 : cs + 2;
        __syncthreads();   // single barrier: orders this iter's writes vs next reads
    }

    // ---- epilogue: accs -> SMEM D (stride-65 f32), per-thread LN + GELU ----
    {
        float* D = (float*)(dynp + OF_D);
        int g = lane >> 2, t2 = (lane & 3) * 2;
#pragma unroll
        for (int mt = 0; mt < 4; mt++)
#pragma unroll
            for (int nt = 0; nt < 4; nt++) {
                int r0 = wr * 64 + mt * 16 + g;
                int c0 = wc * 32 + nt * 8 + t2;
                D[r0 * DSTRIDE + c0]           = acc[mt][nt][0];
                D[r0 * DSTRIDE + c0 + 1]       = acc[mt][nt][1];
                D[(r0 + 8) * DSTRIDE + c0]     = acc[mt][nt][2];
                D[(r0 + 8) * DSTRIDE + c0 + 1] = acc[mt][nt][3];
            }
    }
    __syncthreads();

    {
        const float* Dp = (float*)(dynp + OF_D) + row * DSTRIDE;
        float y[64];
        float s = 0.f, sq = 0.f;
#pragma unroll
        for (int c = 0; c < 64; c++) {
            float v = Dp[c] + cb_s[c];
            y[c] = v;
            s += v;
            sq += v * v;
        }
        float mean = s * (1.0f / 64.0f);
        float var = sq * (1.0f / 64.0f) - mean * mean;
        var = fmaxf(var, 0.0f);
        float inv = rsqrtf(var + 1e-5f);

        float4* og = reinterpret_cast<float4*>(out + (size_t)(rgbase + row) * NW);
#pragma unroll
        for (int q = 0; q < 16; q++) {
            float z0 = (y[4 * q + 0] - mean) * inv * ga_s[4 * q + 0] + be_s[4 * q + 0];
            float z1 = (y[4 * q + 1] - mean) * inv * ga_s[4 * q + 1] + be_s[4 * q + 1];
            float z2 = (y[4 * q + 2] - mean) * inv * ga_s[4 * q + 2] + be_s[4 * q + 2];
            float z3 = (y[4 * q + 3] - mean) * inv * ga_s[4 * q + 3] + be_s[4 * q + 3];
            float4 o;
            o.x = 0.5f * z0 * (1.0f + erff(z0 * 0.70710678118654752f));
            o.y = 0.5f * z1 * (1.0f + erff(z1 * 0.70710678118654752f));
            o.z = 0.5f * z2 * (1.0f + erff(z2 * 0.70710678118654752f));
            o.w = 0.5f * z3 * (1.0f + erff(z3 * 0.70710678118654752f));
            og[q] = o;
        }
    }
}

extern "C" void kernel_launch(void* const* d_in, const int* in_sizes, int n_in,
                              void* d_out, int out_size) {
    const float* X      = (const float*)d_in[0];
    const float* shift  = (const float*)d_in[1];
    const float* lscale = (const float*)d_in[2];
    const float* coef   = (const float*)d_in[3];
    const float* skipW  = (const float*)d_in[4];
    const float* skipb  = (const float*)d_in[5];
    const float* bias   = (const float*)d_in[6];
    const float* gam    = (const float*)d_in[7];
    const float* bet    = (const float*)d_in[8];
    const float* knots  = (const float*)d_in[9];

    cudaFuncSetAttribute(kan_kernel, cudaFuncAttributeMaxDynamicSharedMemorySize,
                         DYN_BYTES);

    prep_kernel<<<256, 256>>>(coef);
    kan_kernel<<<NCTA, NTHREADS, DYN_BYTES>>>(X, shift, lscale, skipW, skipb,
                                              bias, gam, bet, knots,
                                              (float*)d_out);
}

// round 7
// speedup vs baseline: 1.4684x; 1.0208x over previous
#include <cuda_runtime.h>
#include <cuda_bf16.h>
#include <cstdint>

#define NF 64
#define NW 64
#define NBATCH 32768
#define ROWS 256
#define NCTA (NBATCH / ROWS)
#define NTHREADS 512

// ---------------- dynamic SMEM layout (offsets from 1024-aligned base) ------
// 4 basis buffers (bufs 0/1 double as X hi/lo staging in the prologue, and
// the region doubles as the f32 D matrix in the epilogue).
#define OF_A(b) ((b) * 32768)                 // 4 x 32KB basis tiles, SW128
#define OF_C(s) (131072 + (s) * 8192)         // coef ring, 6 slots (48KB)
#define OF_WHI  180224
#define OF_WLO  188416
#define OF_D    0                              // f32 D[256][65] overlay (epilogue)
#define DSTRIDE 65
#define DYN_BYTES (196608 + 1024)

// ---------------- device globals (allocation-free scratch) ------------------
__device__ __align__(16) unsigned short g_coefB[NF * 64 * 64];  // bf16, pre-swizzled [f][w][g]

__device__ __forceinline__ unsigned su(const void* p) {
    return (unsigned)__cvta_generic_to_shared(p);
}
__device__ __forceinline__ unsigned short bfbits(float x) {
    __nv_bfloat16 h = __float2bfloat16(x);
    return *reinterpret_cast<unsigned short*>(&h);
}
__device__ __forceinline__ float bfround(float x) {
    return __bfloat162float(__float2bfloat16(x));
}

// ---------------------------------------------------------------------------
// Prep: spline_coeffs [f][g][w] fp32 -> bf16 B-tiles [f][w-row][g-col],
// SW128 pre-swizzled so a linear cp.async lands them ldmatrix-ready.
// ---------------------------------------------------------------------------
__global__ void prep_kernel(const float* __restrict__ coef) {
    int i0 = blockIdx.x * blockDim.x + threadIdx.x;
    int stride = gridDim.x * blockDim.x;
    for (int i = i0; i < NF * 64 * 64; i += stride) {
        int f = i >> 12, rem = i & 4095, g = rem >> 6, w = rem & 63;
        unsigned o = (unsigned)w * 128u + ((2u * (unsigned)g) ^ (((unsigned)w & 7u) << 4));
        g_coefB[(f << 12) + (o >> 1)] = bfbits(coef[i]);
    }
}

// 8KB coef tile f -> SMEM slot via cp.async (one 16B chunk per thread, 512 thr)
__device__ __forceinline__ void cpa_coef(char* dynp, int slot, int f, int tid) {
    unsigned dst = su(dynp + OF_C(slot)) + tid * 16;
    const char* src = (const char*)(g_coefB + ((size_t)f << 12)) + tid * 16;
    asm volatile("cp.async.cg.shared.global [%0], [%1], 16;"
                 :: "r"(dst), "l"(src) : "memory");
}

__device__ __forceinline__ void hmma(float (&c)[4], const unsigned (&a)[4],
                                     const unsigned (&b)[2]) {
    asm volatile(
        "mma.sync.aligned.m16n8k16.row.col.f32.bf16.bf16.f32 "
        "{%0,%1,%2,%3}, {%4,%5,%6,%7}, {%8,%9}, {%0,%1,%2,%3};"
        : "+f"(c[0]), "+f"(c[1]), "+f"(c[2]), "+f"(c[3])
        : "r"(a[0]), "r"(a[1]), "r"(a[2]), "r"(a[3]), "r"(b[0]), "r"(b[1]));
}

// One 256x64 @ 64x64 -> 256x64 GEMM step, 16 warps, warp tile 32x32.
// A tile: [row][k] bf16, 128B rows, SW128.  B tile: [n][k] bf16, 128B rows, SW128.
__device__ __forceinline__ void gemm64(unsigned abase, unsigned bbase, int lane,
                                       int wr, int wc, float (&acc)[2][4][4]) {
    const unsigned sw = (unsigned)(lane & 7) << 4;
    const unsigned arow = (unsigned)(wr * 32 + (lane & 7) + ((lane >> 3) & 1) * 8);
    const unsigned ac16 = (unsigned)((lane >> 4) << 4);
    const unsigned brow = (unsigned)(wc * 32 + (lane & 7));
    const unsigned bc16 = (unsigned)(((lane >> 3) & 1) << 4);
#pragma unroll
    for (int ks = 0; ks < 4; ks++) {
        unsigned acol = ((unsigned)(ks * 32) + ac16) ^ sw;
        unsigned bcol = ((unsigned)(ks * 32) + bc16) ^ sw;
        unsigned b[4][2];
#pragma unroll
        for (int nt = 0; nt < 4; nt++) {
            unsigned addr = bbase + (brow + nt * 8) * 128u + bcol;
            asm volatile(
                "ldmatrix.sync.aligned.m8n8.x2.shared.b16 {%0,%1}, [%2];"
                : "=r"(b[nt][0]), "=r"(b[nt][1]) : "r"(addr));
        }
#pragma unroll
        for (int mt = 0; mt < 2; mt++) {
            unsigned a[4];
            unsigned addr = abase + (arow + mt * 16) * 128u + acol;
            asm volatile(
                "ldmatrix.sync.aligned.m8n8.x4.shared.b16 {%0,%1,%2,%3}, [%4];"
                : "=r"(a[0]), "=r"(a[1]), "=r"(a[2]), "=r"(a[3]) : "r"(addr));
#pragma unroll
            for (int nt = 0; nt < 4; nt++) hmma(acc[mt][nt], a, b[nt]);
        }
    }
}

// Basis writer: 4 cubic B-spline nonzeros packed into a word-aligned 3-u32
// window (slack slots are true zeros); clears this buffer's previous window.
__device__ __forceinline__ void write_basis(char* Ab, unsigned rx,
                                            const float* xcol, int fb,
                                            const float* sh_s, const float* sc_s,
                                            const float* kn, const float* rcp6,
                                            int& pw) {
    if (pw >= 0) {
        *(unsigned*)(Ab + ((unsigned)(pw + 0) ^ rx)) = 0;
        *(unsigned*)(Ab + ((unsigned)(pw + 4) ^ rx)) = 0;
        if (pw + 8 < 128) *(unsigned*)(Ab + ((unsigned)(pw + 8) ^ rx)) = 0;
    }
    float xv = __ldg(xcol + fb);
    float arg = (xv - sh_s[fb]) * sc_s[fb];
    float xs = __fdividef(1.0f, 1.0f + __expf(-arg));
    int jj = (int)(xs * 61.0f);
    jj = jj < 60 ? jj : 60;
    jj = jj < 0 ? 0 : jj;
    const int j = jj + 3;
    const float* rc = &rcp6[jj * 6];
    float l1 = xs - kn[j], l2 = xs - kn[j - 1], l3 = xs - kn[j - 2];
    float r1 = kn[j + 1] - xs, r2 = kn[j + 2] - xs, r3 = kn[j + 3] - xs;
    float t = rc[0];
    float N0 = r1 * t, N1 = l1 * t;
    t = N0 * rc[1]; N0 = r1 * t; float sv = l2 * t;
    t = N1 * rc[2]; N1 = sv + r2 * t; float N2 = l1 * t;
    t = N0 * rc[3]; N0 = r1 * t; sv = l3 * t;
    t = N1 * rc[4]; N1 = sv + r2 * t; sv = l2 * t;
    t = N2 * rc[5]; N2 = sv + r3 * t; float N3 = l1 * t;
    unsigned b0 = bfbits(N0), b1 = bfbits(N1);
    unsigned b2 = bfbits(N2), b3 = bfbits(N3);
    int wb = (jj >> 1) * 4;
    unsigned w0, w1, w2;
    if (jj & 1) { w0 = b0 << 16; w1 = b1 | (b2 << 16); w2 = b3; }
    else        { w0 = b0 | (b1 << 16); w1 = b2 | (b3 << 16); w2 = 0; }
    *(unsigned*)(Ab + ((unsigned)(wb + 0) ^ rx)) = w0;
    *(unsigned*)(Ab + ((unsigned)(wb + 4) ^ rx)) = w1;
    if (wb + 8 < 128) *(unsigned*)(Ab + ((unsigned)(wb + 8) ^ rx)) = w2;
    pw = wb;
}

// ---------------------------------------------------------------------------
// Fused KAN layer on mma.sync, 16 warps, software-pipelined:
//   per iteration (2 features): thread-half 0 writes basis f+2, half 1 writes
//   f+3 (idle buffer pair), then all 16 warps GEMM features f,f+1 written last
//   iteration; ONE __syncthreads per pair.
// ---------------------------------------------------------------------------
__global__ void __launch_bounds__(NTHREADS, 1) kan_kernel(
    const float* __restrict__ X,
    const float* __restrict__ shift,
    const float* __restrict__ lscale,
    const float* __restrict__ skipW,
    const float* __restrict__ skip_b,
    const float* __restrict__ bias,
    const float* __restrict__ gamma,
    const float* __restrict__ beta,
    const float* __restrict__ knots,
    float* __restrict__ out) {
    extern __shared__ char dynraw[];
    char* dynp = (char*)((((uintptr_t)dynraw) + 1023) & ~(uintptr_t)1023);

    __shared__ float kn[68], rcp6[61 * 6];
    __shared__ float sh_s[64], sc_s[64], cb_s[64], ga_s[64], be_s[64];

    const int tid = threadIdx.x;
    const int lane = tid & 31;
    const int wid = tid >> 5;
    const int wr = wid >> 1, wc = wid & 1;
    const int rgbase = blockIdx.x * ROWS;

    if (tid < 68) kn[tid] = knots[tid];
    if (tid < 64) {
        sh_s[tid] = shift[tid];
        sc_s[tid] = log1pf(__expf(lscale[tid])) + 0.001f;  // softplus + 1e-3
        cb_s[tid] = skip_b[tid] + bias[tid];
        ga_s[tid] = gamma[tid];
        be_s[tid] = beta[tid];
    }
    __syncthreads();
    if (tid < 61) {
        int j = tid + 3;
        rcp6[tid * 6 + 0] = 1.0f / (kn[j + 1] - kn[j]);
        rcp6[tid * 6 + 1] = 1.0f / (kn[j + 1] - kn[j - 1]);
        rcp6[tid * 6 + 2] = 1.0f / (kn[j + 2] - kn[j]);
        rcp6[tid * 6 + 3] = 1.0f / (kn[j + 1] - kn[j - 2]);
        rcp6[tid * 6 + 4] = 1.0f / (kn[j + 2] - kn[j - 1]);
        rcp6[tid * 6 + 5] = 1.0f / (kn[j + 3] - kn[j]);
    }

    const int rowo = tid & 255;            // owned row (two threads per row)
    const int fsel = tid >> 8;             // 0 or 1: which feature of a pair
    const unsigned rx = (unsigned)(rowo & 7) << 4;

    // ---- stage X hi/lo tiles (A layout, SW128) into bufs 0/1 ----
    {
        const float4* xr4 = reinterpret_cast<const float4*>(X + (size_t)(rgbase + rowo) * NF);
        char* xhb = dynp + OF_A(0) + rowo * 128;
        char* xlb = dynp + OF_A(1) + rowo * 128;
        int q0 = fsel * 8;
#pragma unroll
        for (int qq = 0; qq < 8; qq++) {
            int q = q0 + qq;
            float4 v = xr4[q];
            float hx = bfround(v.x), hy = bfround(v.y);
            float hz = bfround(v.z), hw = bfround(v.w);
            unsigned h0 = (unsigned)bfbits(hx) | ((unsigned)bfbits(hy) << 16);
            unsigned h1 = (unsigned)bfbits(hz) | ((unsigned)bfbits(hw) << 16);
            unsigned l0 = (unsigned)bfbits(v.x - hx) | ((unsigned)bfbits(v.y - hy) << 16);
            unsigned l1 = (unsigned)bfbits(v.z - hz) | ((unsigned)bfbits(v.w - hw) << 16);
            unsigned o0 = (unsigned)(8 * q) ^ rx;
            unsigned o1 = (unsigned)(8 * q + 4) ^ rx;
            *(unsigned*)(xhb + o0) = h0;
            *(unsigned*)(xhb + o1) = h1;
            *(unsigned*)(xlb + o0) = l0;
            *(unsigned*)(xlb + o1) = l1;
        }
    }
    // ---- stage skip_W hi/lo (B layout [w][f], SW128) ----
    for (int idx = tid; idx < 4096; idx += NTHREADS) {
        int w = idx >> 6, fcol = idx & 63;
        float v = skipW[idx];               // skip_W is [W][F] row-major
        float h = bfround(v);
        unsigned o = (unsigned)w * 128u + ((2u * (unsigned)fcol) ^ (((unsigned)w & 7u) << 4));
        *(unsigned short*)(dynp + OF_WHI + o) = bfbits(h);
        *(unsigned short*)(dynp + OF_WLO + o) = bfbits(v - h);
    }
    // ---- zero basis bufs 2,3 (not used by skip GEMM) ----
    {
        uint4 z = {0, 0, 0, 0};
        uint4* a2 = reinterpret_cast<uint4*>(dynp + OF_A(2));
        for (int i = tid; i < 4096; i += NTHREADS) a2[i] = z;
    }

    // ---- coef prefetch: pairs (0,1) and (2,3) as two groups ----
    cpa_coef(dynp, 0, 0, tid);
    cpa_coef(dynp, 1, 1, tid);
    asm volatile("cp.async.commit_group;");
    cpa_coef(dynp, 2, 2, tid);
    cpa_coef(dynp, 3, 3, tid);
    asm volatile("cp.async.commit_group;");

    __syncthreads();

    float acc[2][4][4];
#pragma unroll
    for (int mt = 0; mt < 2; mt++)
#pragma unroll
        for (int nt = 0; nt < 4; nt++)
#pragma unroll
            for (int e = 0; e < 4; e++) acc[mt][nt][e] = 0.f;

    // ---- skip GEMM: Xhi@Whi + Xhi@Wlo + Xlo@Whi ----
    gemm64(su(dynp + OF_A(0)), su(dynp + OF_WHI), lane, wr, wc, acc);
    gemm64(su(dynp + OF_A(0)), su(dynp + OF_WLO), lane, wr, wc, acc);
    gemm64(su(dynp + OF_A(1)), su(dynp + OF_WHI), lane, wr, wc, acc);
    __syncthreads();  // all X reads done before reuse as basis tiles

    // zero basis bufs 0,1 (were X staging)
    {
        uint4 z = {0, 0, 0, 0};
        uint4* a0 = reinterpret_cast<uint4*>(dynp + OF_A(0));
        for (int i = tid; i < 4096; i += NTHREADS) a0[i] = z;
    }
    __syncthreads();

    // This thread writes basis for feature pairs into buffers fsel / fsel+2.
    int pwA = -1, pwB = -1;
    const float* xcol = X + (size_t)(rgbase + rowo) * NF;
    char* AbA = dynp + OF_A(fsel) + rowo * 128;       // buf 0 or 1
    char* AbB = dynp + OF_A(fsel + 2) + rowo * 128;   // buf 2 or 3

    // prologue: basis f=0 -> buf0 (threads 0-255), f=1 -> buf1 (256-511)
    write_basis(AbA, rx, xcol, fsel, sh_s, sc_s, kn, rcp6, pwA);
    __syncthreads();

    int cs = 0;  // coef slot of feature f (ring of 6)
    for (int f = 0; f < NF; f += 2) {
        // prefetch coef pair (f+4, f+5)
        if (f + 4 < NF) {
            int ps = cs + 4 >= 6 ? cs - 2 : cs + 4;  // (cs+4) % 6, cs even
            cpa_coef(dynp, ps, f + 4, tid);
            cpa_coef(dynp, ps + 1, f + 5, tid);
        }
        asm volatile("cp.async.commit_group;");

        // write basis for feature f+2+fsel into the idle buffer pair
        if (f + 2 < NF) {
            if (f & 2) write_basis(AbA, rx, xcol, f + 2 + fsel, sh_s, sc_s, kn, rcp6, pwA);
            else       write_basis(AbB, rx, xcol, f + 2 + fsel, sh_s, sc_s, kn, rcp6, pwB);
        }

        asm volatile("cp.async.wait_group 2;");   // coef f, f+1 resident

        // GEMM features f, f+1 (basis written last iteration, coef from ring)
        unsigned ab0 = su(dynp + OF_A(0)) + (unsigned)(f & 2) * 32768u;
        gemm64(ab0, su(dynp + OF_C(0)) + (unsigned)cs * 8192u, lane, wr, wc, acc);
        gemm64(ab0 + 32768u, su(dynp + OF_C(0)) + (unsigned)(cs + 1) * 8192u,
               lane, wr, wc, acc);

        cs = cs + 2 >= 6 ? 0 : cs + 2;
        __syncthreads();   // single barrier: orders this iter's writes vs next reads
    }

    // ---- epilogue: accs -> SMEM D (stride-65 f32), LN + GELU ----
    {
        float* D = (float*)(dynp + OF_D);
        int g = lane >> 2, t2 = (lane & 3) * 2;
#pragma unroll
        for (int mt = 0; mt < 2; mt++)
#pragma unroll
            for (int nt = 0; nt < 4; nt++) {
                int r0 = wr * 32 + mt * 16 + g;
                int c0 = wc * 32 + nt * 8 + t2;
                D[r0 * DSTRIDE + c0]           = acc[mt][nt][0];
                D[r0 * DSTRIDE + c0 + 1]       = acc[mt][nt][1];
                D[(r0 + 8) * DSTRIDE + c0]     = acc[mt][nt][2];
                D[(r0 + 8) * DSTRIDE + c0 + 1] = acc[mt][nt][3];
            }
    }
    __syncthreads();

    {
        const int r = tid >> 1, half = tid & 1, cb = half * 32;
        const float* Dp = (float*)(dynp + OF_D) + r * DSTRIDE + cb;
        float y[32];
        float s = 0.f, sq = 0.f;
#pragma unroll
        for (int c = 0; c < 32; c++) {
            float v = Dp[c] + cb_s[cb + c];
            y[c] = v;
            s += v;
            sq += v * v;
        }
        s += __shfl_xor_sync(0xffffffffu, s, 1);
        sq += __shfl_xor_sync(0xffffffffu, sq, 1);
        float mean = s * (1.0f / 64.0f);
        float var = sq * (1.0f / 64.0f) - mean * mean;
        var = fmaxf(var, 0.0f);
        float inv = rsqrtf(var + 1e-5f);

        float4* og = reinterpret_cast<float4*>(out + (size_t)(rgbase + r) * NW + cb);
#pragma unroll
        for (int q = 0; q < 8; q++) {
            float z0 = (y[4 * q + 0] - mean) * inv * ga_s[cb + 4 * q + 0] + be_s[cb + 4 * q + 0];
            float z1 = (y[4 * q + 1] - mean) * inv * ga_s[cb + 4 * q + 1] + be_s[cb + 4 * q + 1];
            float z2 = (y[4 * q + 2] - mean) * inv * ga_s[cb + 4 * q + 2] + be_s[cb + 4 * q + 2];
            float z3 = (y[4 * q + 3] - mean) * inv * ga_s[cb + 4 * q + 3] + be_s[cb + 4 * q + 3];
            float4 o;
            o.x = 0.5f * z0 * (1.0f + erff(z0 * 0.70710678118654752f));
            o.y = 0.5f * z1 * (1.0f + erff(z1 * 0.70710678118654752f));
            o.z = 0.5f * z2 * (1.0f + erff(z2 * 0.70710678118654752f));
            o.w = 0.5f * z3 * (1.0f + erff(z3 * 0.70710678118654752f));
            og[q] = o;
        }
    }
}

extern "C" void kernel_launch(void* const* d_in, const int* in_sizes, int n_in,
                              void* d_out, int out_size) {
    const float* X      = (const float*)d_in[0];
    const float* shift  = (const float*)d_in[1];
    const float* lscale = (const float*)d_in[2];
    const float* coef   = (const float*)d_in[3];
    const float* skipW  = (const float*)d_in[4];
    const float* skipb  = (const float*)d_in[5];
    const float* bias   = (const float*)d_in[6];
    const float* gam    = (const float*)d_in[7];
    const float* bet    = (const float*)d_in[8];
    const float* knots  = (const float*)d_in[9];

    cudaFuncSetAttribute(kan_kernel, cudaFuncAttributeMaxDynamicSharedMemorySize,
                         DYN_BYTES);

    prep_kernel<<<256, 256>>>(coef);
    kan_kernel<<<NCTA, NTHREADS, DYN_BYTES>>>(X, shift, lscale, skipW, skipb,
                                              bias, gam, bet, knots,
                                              (float*)d_out);
}